// round 10
// baseline (speedup 1.0000x reference)
#include <cuda_runtime.h>
#include <cuda_bf16.h>
#include <math.h>
#include <stdint.h>

// Problem constants
#define BATCH 32
#define TLEN  256
#define HID   768
#define H     128
#define G3    384   // 3*H
#define NL    9

#define NEG_INF (-1e30f)

// ---------------- scratch (device globals; no allocations allowed) ----------
__device__ float g_xp[2 * TLEN * BATCH * G3];     // [dir][step][b][g]  25.2MB
__device__ float g_hcat[BATCH * TLEN * 2 * H];    // [b][t][256]        8.4MB
__device__ float g_em[BATCH * TLEN * NL];         // emissions
__device__ float g_llh[BATCH];
__device__ __nv_bfloat16 g_wbf[2 * G3 * HID];     // [n][k] bf16 weights (f then b)
__device__ __nv_bfloat16 g_abf[BATCH * TLEN * HID]; // gathered A in bf16 (12.6MB)

// ---------------------------------------------------------------------------
// K0a: convert Wih_f / Wih_b -> bf16 panel  [768][768]
// ---------------------------------------------------------------------------
__global__ void conv_w_kernel(const float* __restrict__ Wf, const float* __restrict__ Wb)
{
    int n = blockIdx.x;           // 0..767
    int k = threadIdx.x;          // 0..767
    float v = (n < G3) ? Wf[n * HID + k] : Wb[(n - G3) * HID + k];
    g_wbf[(size_t)n * HID + k] = __float2bfloat16(v);
}

// ---------------------------------------------------------------------------
// K0b: gather emb rows by input_ids and convert to bf16 -> g_abf [8192][768]
// ---------------------------------------------------------------------------
__global__ __launch_bounds__(192) void conv_a_kernel(
    const int* __restrict__ ids, const float* __restrict__ emb)
{
    int m = blockIdx.x;                  // 0..8191
    int row = __ldg(&ids[m]);
    const float4* src = (const float4*)(emb + (size_t)row * HID);
    float4 v = src[threadIdx.x];
    __nv_bfloat162 lo = __float22bfloat162_rn(make_float2(v.x, v.y));
    __nv_bfloat162 hi = __float22bfloat162_rn(make_float2(v.z, v.w));
    uint2 u;
    u.x = *(uint32_t*)&lo; u.y = *(uint32_t*)&hi;
    *(uint2*)(g_abf + (size_t)m * HID + threadIdx.x * 4) = u;
}

// ---------------------------------------------------------------------------
// K1: input projection GEMM on tensor cores (bf16 HMMA), all-cp.async 3-stage.
// ---------------------------------------------------------------------------
#define BM 128
#define BN 128
#define BKC 32
#define ASZ (BM * BKC)   // bf16 elements per stage buffer
#define NK (HID / BKC)   // 24

__device__ __forceinline__ void ldsm4(uint32_t* r, uint32_t addr) {
    asm volatile("ldmatrix.sync.aligned.m8n8.x4.shared.b16 {%0,%1,%2,%3}, [%4];\n"
                 : "=r"(r[0]), "=r"(r[1]), "=r"(r[2]), "=r"(r[3]) : "r"(addr));
}
__device__ __forceinline__ void mma16816(float* c, const uint32_t* a, const uint32_t* b) {
    asm volatile(
        "mma.sync.aligned.m16n8k16.row.col.f32.bf16.bf16.f32 "
        "{%0,%1,%2,%3}, {%4,%5,%6,%7}, {%8,%9}, {%0,%1,%2,%3};\n"
        : "+f"(c[0]), "+f"(c[1]), "+f"(c[2]), "+f"(c[3])
        : "r"(a[0]), "r"(a[1]), "r"(a[2]), "r"(a[3]), "r"(b[0]), "r"(b[1]));
}
__device__ __forceinline__ void cpasync16(uint32_t dst, const void* src) {
    asm volatile("cp.async.ca.shared.global [%0], [%1], 16;\n" :: "r"(dst), "l"(src));
}

__global__ __launch_bounds__(256) void gemm_xp_tc(
    const float* __restrict__ bih_f, const float* __restrict__ bih_b)
{
    __shared__ __align__(16) __nv_bfloat16 As[3 * ASZ];
    __shared__ __align__(16) __nv_bfloat16 Bs[3 * ASZ];

    const int tid = threadIdx.x;
    const int m0 = blockIdx.x * BM;
    const int n0 = blockIdx.y * BN;

    const int lrow = tid >> 1;          // 0..127
    const int cpa  = (tid & 1) * 2;     // chunk base: 0 or 2 (8 bf16 per chunk)

    const __nv_bfloat16* aptr = g_abf + (size_t)(m0 + lrow) * HID + cpa * 8;
    const __nv_bfloat16* bptr = g_wbf + (size_t)(n0 + lrow) * HID + cpa * 8;

    const uint32_t as_base = (uint32_t)__cvta_generic_to_shared(As);
    const uint32_t bs_base = (uint32_t)__cvta_generic_to_shared(Bs);

    const int swz = (lrow >> 1) & 3;
    const uint32_t off0 = (uint32_t)((lrow * BKC + ((cpa ^ swz) << 3)) * 2);
    const uint32_t off1 = (uint32_t)((lrow * BKC + (((cpa + 1) ^ swz) << 3)) * 2);

    const int warp = tid >> 5, lane = tid & 31;
    const int wm = warp >> 2, wn = warp & 3;   // 2 x 4
    const int lr = lane & 7, lmi = lane >> 3;

    float acc[4][4][4];
#pragma unroll
    for (int i = 0; i < 4; i++)
#pragma unroll
        for (int j = 0; j < 4; j++)
#pragma unroll
            for (int q = 0; q < 4; q++) acc[i][j][q] = 0.f;

#pragma unroll
    for (int s = 0; s < 2; s++) {
        uint32_t sb = s * (ASZ * 2);
        cpasync16(as_base + sb + off0, aptr + s * BKC);
        cpasync16(as_base + sb + off1, aptr + s * BKC + 8);
        cpasync16(bs_base + sb + off0, bptr + s * BKC);
        cpasync16(bs_base + sb + off1, bptr + s * BKC + 8);
        asm volatile("cp.async.commit_group;\n");
    }

    int sc = 0;
    int si = 2;
    for (int ch = 0; ch < NK; ch++) {
        __syncthreads();
        if (ch + 2 < NK) {
            const uint32_t sb = si * (ASZ * 2);
            const int kk = (ch + 2) * BKC;
            cpasync16(as_base + sb + off0, aptr + kk);
            cpasync16(as_base + sb + off1, aptr + kk + 8);
            cpasync16(bs_base + sb + off0, bptr + kk);
            cpasync16(bs_base + sb + off1, bptr + kk + 8);
            asm volatile("cp.async.commit_group;\n");
            asm volatile("cp.async.wait_group 2;\n");
            si = (si == 2) ? 0 : si + 1;
        } else {
            asm volatile("cp.async.wait_group 0;\n");
        }
        __syncthreads();

        const uint32_t ab = as_base + sc * (ASZ * 2);
        const uint32_t bb = bs_base + sc * (ASZ * 2);
#pragma unroll
        for (int k16 = 0; k16 < 2; k16++) {
            uint32_t afr[4][4];
#pragma unroll
            for (int am = 0; am < 4; am++) {
                int rowA = wm * 64 + am * 16 + lr + ((lmi & 1) << 3);
                int cA = k16 * 2 + (lmi >> 1);
                uint32_t addr = ab + (uint32_t)((rowA * BKC + ((cA ^ ((rowA >> 1) & 3)) << 3)) * 2);
                ldsm4(afr[am], addr);
            }
            uint32_t bfr[4][2];
#pragma unroll
            for (int p = 0; p < 2; p++) {
                int rowB = wn * 32 + p * 16 + lr + ((lmi >> 1) << 3);
                int cB = k16 * 2 + (lmi & 1);
                uint32_t addr = bb + (uint32_t)((rowB * BKC + ((cB ^ ((rowB >> 1) & 3)) << 3)) * 2);
                uint32_t r[4];
                ldsm4(r, addr);
                bfr[2 * p][0] = r[0]; bfr[2 * p][1] = r[1];
                bfr[2 * p + 1][0] = r[2]; bfr[2 * p + 1][1] = r[3];
            }
#pragma unroll
            for (int am = 0; am < 4; am++)
#pragma unroll
                for (int an = 0; an < 4; an++)
                    mma16816(acc[am][an], afr[am], bfr[an]);
        }
        sc = (sc == 2) ? 0 : sc + 1;
    }

#pragma unroll
    for (int am = 0; am < 4; am++) {
#pragma unroll
        for (int an = 0; an < 4; an++) {
            int n = n0 + wn * 32 + an * 8 + (lane & 3) * 2;
            int dir = (n >= G3) ? 1 : 0;
            int g = n - dir * G3;
            float b0 = dir ? bih_b[g] : bih_f[g];
            float b1 = dir ? bih_b[g + 1] : bih_f[g + 1];
#pragma unroll
            for (int half = 0; half < 2; half++) {
                int m = m0 + wm * 64 + am * 16 + (lane >> 2) + half * 8;
                int b = m >> 8, t = m & 255;
                int step = dir ? (TLEN - 1 - t) : t;
                float2 v;
                v.x = acc[am][an][2 * half + 0] + b0;
                v.y = acc[am][an][2 * half + 1] + b1;
                *(float2*)&g_xp[(((size_t)dir * TLEN + step) * BATCH + b) * G3 + g] = v;
            }
        }
    }
}

// ---------------------------------------------------------------------------
// K2: GRU recurrence, K-split x2: 768 threads, thread (row, khalf) computes
//     half of Whh row `row` dot h. 24 warps hide LDS latency; w2 = 64 regs.
//     Partials in ghs2[row*2+khalf]; activation threads (tid<128) combine.
// ---------------------------------------------------------------------------
__device__ __forceinline__ uint64_t packf2(float lo, float hi) {
    uint64_t u;
    asm("mov.b64 %0, {%1,%2};" : "=l"(u)
        : "r"(__float_as_uint(lo)), "r"(__float_as_uint(hi)));
    return u;
}
__device__ __forceinline__ void fma2(uint64_t& d, uint64_t a, uint64_t b) {
    asm("fma.rn.f32x2 %0, %1, %2, %0;" : "+l"(d) : "l"(a), "l"(b));
}
__device__ __forceinline__ float tanh_fast(float x) {
    float y;
    asm("tanh.approx.f32 %0, %1;" : "=f"(y) : "f"(x));
    return y;
}
__device__ __forceinline__ float sigmoid_fast(float x) {
    return fmaf(0.5f, tanh_fast(0.5f * x), 0.5f);
}

__global__ __launch_bounds__(768, 1) void gru_kernel(
    const float* __restrict__ Whh_f, const float* __restrict__ bhh_f,
    const float* __restrict__ Whh_b, const float* __restrict__ bhh_b)
{
    const int b   = blockIdx.x & 31;
    const int dir = blockIdx.x >> 5;
    const float* Whh = dir ? Whh_b : Whh_f;
    const float* bhh = dir ? bhh_b : bhh_f;
    const int tid = threadIdx.x;
    const int row = tid >> 1;      // 0..383 (gate-row)
    const int kh  = tid & 1;       // K half: [0,64) or [64,128)

    // load this thread's 64 weights as 32 packed f32x2 pairs
    uint64_t w2[32];
    {
        const ulonglong2* wsrc = (const ulonglong2*)(Whh + (size_t)row * H + kh * 64);
#pragma unroll
        for (int j = 0; j < 16; j++) {
            ulonglong2 p = wsrc[j];
            w2[2 * j] = p.x; w2[2 * j + 1] = p.y;
        }
    }
    const float bias0 = (kh == 0) ? bhh[row] : 0.f;
    const bool do_xadd = (kh == 0) & (row < 2 * H);   // pre-add x for r,z rows
    const bool do_xsn  = (kh == 0) & (row >= 2 * H);  // n rows: stash x

    __shared__ __align__(16) float hs[H];
    __shared__ __align__(8)  float ghs2[2 * G3];
    __shared__ float xsn[H];

    if (tid < H) hs[tid] = 0.f;
    float hprev = 0.f;    // activation thread g=tid keeps h[g] in register

    const float* xp = g_xp + ((size_t)dir * TLEN * BATCH + b) * G3;
    float xnext = (kh == 0) ? xp[row] : 0.f;
    __syncthreads();

    const ulonglong2* h4 = (const ulonglong2*)hs + kh * 16;  // 16 x 16B = 64 floats

    for (int t = 0; t < TLEN; t++) {
        float xt = xnext;
        if (kh == 0 && t < TLEN - 1) xnext = xp[(size_t)(t + 1) * BATCH * G3 + row];
        if (do_xsn) xsn[row - 2 * H] = xt;

        // half-row dot product: 32 packed FMA2 over 16 LDS.128
        uint64_t acc_a = packf2(do_xadd ? (bias0 + xt) : bias0, 0.f);
        uint64_t acc_b = packf2(0.f, 0.f);
#pragma unroll
        for (int j = 0; j < 16; j++) {
            ulonglong2 p = h4[j];
            fma2(acc_a, w2[2 * j], p.x);
            fma2(acc_b, w2[2 * j + 1], p.y);
        }
        uint32_t alo, ahi, blo, bhi;
        asm("mov.b64 {%0,%1}, %2;" : "=r"(alo), "=r"(ahi) : "l"(acc_a));
        asm("mov.b64 {%0,%1}, %2;" : "=r"(blo), "=r"(bhi) : "l"(acc_b));
        ghs2[tid] = (__uint_as_float(alo) + __uint_as_float(ahi)) +
                    (__uint_as_float(blo) + __uint_as_float(bhi));
        __syncthreads();

        if (tid < H) {
            float2 pr = *(const float2*)&ghs2[2 * tid];            // bias+x+dot (r)
            float2 pz = *(const float2*)&ghs2[2 * (tid + H)];      // bias+x+dot (z)
            float2 pn = *(const float2*)&ghs2[2 * (tid + 2 * H)];  // bias+dot   (n)
            float r = sigmoid_fast(pr.x + pr.y);
            float z = sigmoid_fast(pz.x + pz.y);
            float n = tanh_fast(xsn[tid] + r * (pn.x + pn.y));
            float hnew = (1.f - z) * n + z * hprev;
            hprev = hnew;
            hs[tid] = hnew;
            int tt = dir ? (TLEN - 1 - t) : t;
            g_hcat[((size_t)b * TLEN + tt) * (2 * H) + dir * H + tid] = hnew;
        }
        __syncthreads();
    }
}

// ---------------------------------------------------------------------------
// K3: emissions = hcat @ Wlin^T + blin  (M=8192, N=9, K=256). Warp per row.
// ---------------------------------------------------------------------------
__global__ __launch_bounds__(256) void emis_kernel(
    const float* __restrict__ Wlin, const float* __restrict__ blin)
{
    __shared__ float wl[NL][2 * H];
    __shared__ float bl[NL];
    const int tid = threadIdx.x;
    for (int i = tid; i < NL * 2 * H; i += 256) wl[i / (2 * H)][i % (2 * H)] = Wlin[i];
    if (tid < NL) bl[tid] = blin[tid];
    __syncthreads();

    const int warp = tid >> 5, lane = tid & 31;
    const int row = blockIdx.x * 8 + warp;   // b*256 + t
    const float* h = g_hcat + (size_t)row * (2 * H);
    float hv[8];
#pragma unroll
    for (int i = 0; i < 8; i++) hv[i] = h[i * 32 + lane];
#pragma unroll
    for (int l = 0; l < NL; l++) {
        float s = 0.f;
#pragma unroll
        for (int i = 0; i < 8; i++) s += hv[i] * wl[l][i * 32 + lane];
#pragma unroll
        for (int off = 16; off; off >>= 1) s += __shfl_xor_sync(0xffffffffu, s, off);
        if (lane == 0) g_em[(size_t)row * NL + l] = s + bl[l];
    }
}

// ---------------------------------------------------------------------------
// K4: Viterbi + CRF log-likelihood, 8 warps per block (4 Viterbi + 4 CRF).
// ---------------------------------------------------------------------------
__global__ __launch_bounds__(256) void vitcrf_kernel(
    const float* __restrict__ trans, const float* __restrict__ startv,
    const float* __restrict__ endv, const int* __restrict__ labels,
    float* __restrict__ dout)
{
    const int w    = threadIdx.x >> 5;
    const int lane = threadIdx.x & 31;
    const int b    = blockIdx.x * 4 + (w >> 1);   // batch index
    const bool isV = (w & 1) == 0;

    float tr[NL];
#pragma unroll
    for (int i = 0; i < NL; i++) tr[i] = (lane < NL) ? trans[i * NL + lane] : 0.f;

    const float* em = g_em + (size_t)b * TLEN * NL;

    if (isV) {
        __shared__ unsigned char bp[4][TLEN - 1][NL];
        const int vw = w >> 1;
        float alpha = (lane < NL) ? startv[lane] + em[lane] : NEG_INF;
        float ecur = (lane < NL) ? em[NL + lane] : 0.f;
        for (int t = 1; t < TLEN; t++) {
            float enext = (t < TLEN - 1 && lane < NL) ? em[(t + 1) * NL + lane] : 0.f;
            float best = NEG_INF; int bi = 0;
#pragma unroll
            for (int i = 0; i < NL; i++) {
                float ai = __shfl_sync(0xffffffffu, alpha, i);
                float sc = ai + tr[i];
                if (sc > best) { best = sc; bi = i; }
            }
            if (lane < NL) {
                bp[vw][t - 1][lane] = (unsigned char)bi;
                alpha = best + ecur;
            }
            ecur = enext;
        }
        float v = (lane < NL) ? alpha + endv[lane] : NEG_INF;
        int idx = lane;
#pragma unroll
        for (int off = 16; off; off >>= 1) {
            float ov = __shfl_xor_sync(0xffffffffu, v, off);
            int   oi = __shfl_xor_sync(0xffffffffu, idx, off);
            if (ov > v || (ov == v && oi < idx)) { v = ov; idx = oi; }
        }
        __syncwarp();
        if (lane == 0) {
            int y = idx;
            float* outp = dout + b * TLEN;
            outp[TLEN - 1] = (float)y;
            for (int t = TLEN - 2; t >= 0; t--) {
                y = bp[vw][t][y];
                outp[t] = (float)y;
            }
        }
    } else {
        const int* lab = labels + b * TLEN;
        float s = 0.f;
        for (int t = lane; t < TLEN; t += 32) s += em[t * NL + lab[t]];
        for (int t = lane; t < TLEN - 1; t += 32) s += trans[lab[t] * NL + lab[t + 1]];
#pragma unroll
        for (int off = 16; off; off >>= 1) s += __shfl_xor_sync(0xffffffffu, s, off);
        float num = s + startv[lab[0]] + endv[lab[TLEN - 1]];

        float ca = (lane < NL) ? startv[lane] + em[lane] : NEG_INF;
        float ecur = (lane < NL) ? em[NL + lane] : 0.f;
        for (int t = 1; t < TLEN; t++) {
            float enext = (t < TLEN - 1 && lane < NL) ? em[(t + 1) * NL + lane] : 0.f;
            float vals[NL];
#pragma unroll
            for (int i = 0; i < NL; i++) {
                float ai = __shfl_sync(0xffffffffu, ca, i);
                vals[i] = ai + tr[i];
            }
            float m01 = fmaxf(vals[0], vals[1]), m23 = fmaxf(vals[2], vals[3]);
            float m45 = fmaxf(vals[4], vals[5]), m67 = fmaxf(vals[6], vals[7]);
            float m0123 = fmaxf(m01, m23), m4567 = fmaxf(m45, m67);
            float best = fmaxf(fmaxf(m0123, m4567), vals[8]);
            float ssum = 0.f;
#pragma unroll
            for (int i = 0; i < NL; i++) ssum += __expf(vals[i] - best);
            ca = (lane < NL) ? (best + __logf(ssum) + ecur) : NEG_INF;
            ecur = enext;
        }
        float v = (lane < NL) ? ca + endv[lane] : NEG_INF;
        float m = v;
#pragma unroll
        for (int off = 16; off; off >>= 1) m = fmaxf(m, __shfl_xor_sync(0xffffffffu, m, off));
        float ex = (lane < NL) ? __expf(v - m) : 0.f;
#pragma unroll
        for (int off = 16; off; off >>= 1) ex += __shfl_xor_sync(0xffffffffu, ex, off);
        if (lane == 0) g_llh[b] = num - (m + __logf(ex));
    }
}

// ---------------------------------------------------------------------------
// K5: loss = -mean(llh)
// ---------------------------------------------------------------------------
__global__ void loss_kernel(float* __restrict__ dout, int out_size)
{
    float v = g_llh[threadIdx.x];
#pragma unroll
    for (int off = 16; off; off >>= 1) v += __shfl_xor_sync(0xffffffffu, v, off);
    if (threadIdx.x == 0) dout[out_size - 1] = -(v / (float)BATCH);
}

// ---------------------------------------------------------------------------
extern "C" void kernel_launch(void* const* d_in, const int* in_sizes, int n_in,
                              void* d_out, int out_size)
{
    const int*   input_ids = (const int*)d_in[0];
    const int*   labels    = (const int*)d_in[2];
    const float* emb       = (const float*)d_in[3];
    const float* Wih_f     = (const float*)d_in[4];
    const float* Whh_f     = (const float*)d_in[5];
    const float* bih_f     = (const float*)d_in[6];
    const float* bhh_f     = (const float*)d_in[7];
    const float* Wih_b     = (const float*)d_in[8];
    const float* Whh_b     = (const float*)d_in[9];
    const float* bih_b     = (const float*)d_in[10];
    const float* bhh_b     = (const float*)d_in[11];
    const float* Wlin      = (const float*)d_in[12];
    const float* blin      = (const float*)d_in[13];
    const float* trans     = (const float*)d_in[14];
    const float* startv    = (const float*)d_in[15];
    const float* endv      = (const float*)d_in[16];
    float* out = (float*)d_out;

    conv_w_kernel<<<2 * G3, HID>>>(Wih_f, Wih_b);
    conv_a_kernel<<<BATCH * TLEN, 192>>>(input_ids, emb);
    dim3 ggrid((BATCH * TLEN) / BM, (2 * G3) / BN);
    gemm_xp_tc<<<ggrid, 256>>>(bih_f, bih_b);
    gru_kernel<<<64, 768>>>(Whh_f, bhh_f, Whh_b, bhh_b);
    emis_kernel<<<BATCH * TLEN / 8, 256>>>(Wlin, blin);
    vitcrf_kernel<<<8, 256>>>(trans, startv, endv, labels, out);
    loss_kernel<<<1, 32>>>(out, out_size);
}

// round 12
// speedup vs baseline: 1.7993x; 1.7993x over previous
#include <cuda_runtime.h>
#include <cuda_bf16.h>
#include <math.h>
#include <stdint.h>

// Problem constants
#define BATCH 32
#define TLEN  256
#define HID   768
#define H     128
#define G3    384   // 3*H
#define NL    9

#define NEG_INF (-1e30f)

// ---------------- scratch (device globals; no allocations allowed) ----------
__device__ float g_xp[2 * TLEN * BATCH * G3];     // [dir][step][b][g]  25.2MB
__device__ float g_hcat[BATCH * TLEN * 2 * H];    // [b][t][256]        8.4MB
__device__ float g_em[BATCH * TLEN * NL];         // emissions
__device__ float g_llh[BATCH];
__device__ __nv_bfloat16 g_wbf[2 * G3 * HID];     // [n][k] bf16 weights (f then b)
__device__ __nv_bfloat16 g_abf[BATCH * TLEN * HID]; // gathered A in bf16 (12.6MB)

// ---------------------------------------------------------------------------
// K0a: convert Wih_f / Wih_b -> bf16 panel  [768][768]
// ---------------------------------------------------------------------------
__global__ void conv_w_kernel(const float* __restrict__ Wf, const float* __restrict__ Wb)
{
    int n = blockIdx.x;           // 0..767
    int k = threadIdx.x;          // 0..767
    float v = (n < G3) ? Wf[n * HID + k] : Wb[(n - G3) * HID + k];
    g_wbf[(size_t)n * HID + k] = __float2bfloat16(v);
}

// ---------------------------------------------------------------------------
// K0b: gather emb rows by input_ids and convert to bf16 -> g_abf [8192][768]
// ---------------------------------------------------------------------------
__global__ __launch_bounds__(192) void conv_a_kernel(
    const int* __restrict__ ids, const float* __restrict__ emb)
{
    int m = blockIdx.x;                  // 0..8191
    int row = __ldg(&ids[m]);
    const float4* src = (const float4*)(emb + (size_t)row * HID);
    float4 v = src[threadIdx.x];
    __nv_bfloat162 lo = __float22bfloat162_rn(make_float2(v.x, v.y));
    __nv_bfloat162 hi = __float22bfloat162_rn(make_float2(v.z, v.w));
    uint2 u;
    u.x = *(uint32_t*)&lo; u.y = *(uint32_t*)&hi;
    *(uint2*)(g_abf + (size_t)m * HID + threadIdx.x * 4) = u;
}

// ---------------------------------------------------------------------------
// K1: input projection GEMM on tensor cores (bf16 HMMA), all-cp.async 3-stage.
//     Epilogue folds bih (always) and bhh (for r,z gate rows g<256) into g_xp.
// ---------------------------------------------------------------------------
#define BM 128
#define BN 128
#define BKC 32
#define ASZ (BM * BKC)   // bf16 elements per stage buffer
#define NK (HID / BKC)   // 24

__device__ __forceinline__ void ldsm4(uint32_t* r, uint32_t addr) {
    asm volatile("ldmatrix.sync.aligned.m8n8.x4.shared.b16 {%0,%1,%2,%3}, [%4];\n"
                 : "=r"(r[0]), "=r"(r[1]), "=r"(r[2]), "=r"(r[3]) : "r"(addr));
}
__device__ __forceinline__ void mma16816(float* c, const uint32_t* a, const uint32_t* b) {
    asm volatile(
        "mma.sync.aligned.m16n8k16.row.col.f32.bf16.bf16.f32 "
        "{%0,%1,%2,%3}, {%4,%5,%6,%7}, {%8,%9}, {%0,%1,%2,%3};\n"
        : "+f"(c[0]), "+f"(c[1]), "+f"(c[2]), "+f"(c[3])
        : "r"(a[0]), "r"(a[1]), "r"(a[2]), "r"(a[3]), "r"(b[0]), "r"(b[1]));
}
__device__ __forceinline__ void cpasync16(uint32_t dst, const void* src) {
    asm volatile("cp.async.ca.shared.global [%0], [%1], 16;\n" :: "r"(dst), "l"(src));
}

__global__ __launch_bounds__(256) void gemm_xp_tc(
    const float* __restrict__ bih_f, const float* __restrict__ bih_b,
    const float* __restrict__ bhh_f, const float* __restrict__ bhh_b)
{
    __shared__ __align__(16) __nv_bfloat16 As[3 * ASZ];
    __shared__ __align__(16) __nv_bfloat16 Bs[3 * ASZ];

    const int tid = threadIdx.x;
    const int m0 = blockIdx.x * BM;
    const int n0 = blockIdx.y * BN;

    const int lrow = tid >> 1;          // 0..127
    const int cpa  = (tid & 1) * 2;     // chunk base: 0 or 2 (8 bf16 per chunk)

    const __nv_bfloat16* aptr = g_abf + (size_t)(m0 + lrow) * HID + cpa * 8;
    const __nv_bfloat16* bptr = g_wbf + (size_t)(n0 + lrow) * HID + cpa * 8;

    const uint32_t as_base = (uint32_t)__cvta_generic_to_shared(As);
    const uint32_t bs_base = (uint32_t)__cvta_generic_to_shared(Bs);

    const int swz = (lrow >> 1) & 3;
    const uint32_t off0 = (uint32_t)((lrow * BKC + ((cpa ^ swz) << 3)) * 2);
    const uint32_t off1 = (uint32_t)((lrow * BKC + (((cpa + 1) ^ swz) << 3)) * 2);

    const int warp = tid >> 5, lane = tid & 31;
    const int wm = warp >> 2, wn = warp & 3;   // 2 x 4
    const int lr = lane & 7, lmi = lane >> 3;

    float acc[4][4][4];
#pragma unroll
    for (int i = 0; i < 4; i++)
#pragma unroll
        for (int j = 0; j < 4; j++)
#pragma unroll
            for (int q = 0; q < 4; q++) acc[i][j][q] = 0.f;

#pragma unroll
    for (int s = 0; s < 2; s++) {
        uint32_t sb = s * (ASZ * 2);
        cpasync16(as_base + sb + off0, aptr + s * BKC);
        cpasync16(as_base + sb + off1, aptr + s * BKC + 8);
        cpasync16(bs_base + sb + off0, bptr + s * BKC);
        cpasync16(bs_base + sb + off1, bptr + s * BKC + 8);
        asm volatile("cp.async.commit_group;\n");
    }

    int sc = 0;
    int si = 2;
    for (int ch = 0; ch < NK; ch++) {
        __syncthreads();
        if (ch + 2 < NK) {
            const uint32_t sb = si * (ASZ * 2);
            const int kk = (ch + 2) * BKC;
            cpasync16(as_base + sb + off0, aptr + kk);
            cpasync16(as_base + sb + off1, aptr + kk + 8);
            cpasync16(bs_base + sb + off0, bptr + kk);
            cpasync16(bs_base + sb + off1, bptr + kk + 8);
            asm volatile("cp.async.commit_group;\n");
            asm volatile("cp.async.wait_group 2;\n");
            si = (si == 2) ? 0 : si + 1;
        } else {
            asm volatile("cp.async.wait_group 0;\n");
        }
        __syncthreads();

        const uint32_t ab = as_base + sc * (ASZ * 2);
        const uint32_t bb = bs_base + sc * (ASZ * 2);
#pragma unroll
        for (int k16 = 0; k16 < 2; k16++) {
            uint32_t afr[4][4];
#pragma unroll
            for (int am = 0; am < 4; am++) {
                int rowA = wm * 64 + am * 16 + lr + ((lmi & 1) << 3);
                int cA = k16 * 2 + (lmi >> 1);
                uint32_t addr = ab + (uint32_t)((rowA * BKC + ((cA ^ ((rowA >> 1) & 3)) << 3)) * 2);
                ldsm4(afr[am], addr);
            }
            uint32_t bfr[4][2];
#pragma unroll
            for (int p = 0; p < 2; p++) {
                int rowB = wn * 32 + p * 16 + lr + ((lmi >> 1) << 3);
                int cB = k16 * 2 + (lmi & 1);
                uint32_t addr = bb + (uint32_t)((rowB * BKC + ((cB ^ ((rowB >> 1) & 3)) << 3)) * 2);
                uint32_t r[4];
                ldsm4(r, addr);
                bfr[2 * p][0] = r[0]; bfr[2 * p][1] = r[1];
                bfr[2 * p + 1][0] = r[2]; bfr[2 * p + 1][1] = r[3];
            }
#pragma unroll
            for (int am = 0; am < 4; am++)
#pragma unroll
                for (int an = 0; an < 4; an++)
                    mma16816(acc[am][an], afr[am], bfr[an]);
        }
        sc = (sc == 2) ? 0 : sc + 1;
    }

#pragma unroll
    for (int am = 0; am < 4; am++) {
#pragma unroll
        for (int an = 0; an < 4; an++) {
            int n = n0 + wn * 32 + an * 8 + (lane & 3) * 2;
            int dir = (n >= G3) ? 1 : 0;
            int g = n - dir * G3;
            float b0 = dir ? bih_b[g] : bih_f[g];
            float b1 = dir ? bih_b[g + 1] : bih_f[g + 1];
            // fold bhh for r,z gate rows (g < 2H); n-gate bias stays in gru.
            if (g < 2 * H) {
                b0 += dir ? bhh_b[g] : bhh_f[g];
                b1 += dir ? bhh_b[g + 1] : bhh_f[g + 1];
            }
#pragma unroll
            for (int half = 0; half < 2; half++) {
                int m = m0 + wm * 64 + am * 16 + (lane >> 2) + half * 8;
                int b = m >> 8, t = m & 255;
                int step = dir ? (TLEN - 1 - t) : t;
                float2 v;
                v.x = acc[am][an][2 * half + 0] + b0;
                v.y = acc[am][an][2 * half + 1] + b1;
                *(float2*)&g_xp[(((size_t)dir * TLEN + step) * BATCH + b) * G3 + g] = v;
            }
        }
    }
}

// ---------------------------------------------------------------------------
// K2: GRU recurrence — 512 threads, 4-thread groups per column (c, K-quarter q).
//     Each thread: quarter-dots for all 3 gates (48 FMA2), shfl-butterfly
//     reduction within the group, redundant activation, ONE barrier per step,
//     ping-pong h buffers (padded, conflict-free).
// ---------------------------------------------------------------------------
__device__ __forceinline__ void fma2(uint64_t& d, uint64_t a, uint64_t b) {
    asm("fma.rn.f32x2 %0, %1, %2, %0;" : "+l"(d) : "l"(a), "l"(b));
}
__device__ __forceinline__ float lohi_sum(uint64_t v) {
    uint32_t lo, hi;
    asm("mov.b64 {%0,%1}, %2;" : "=r"(lo), "=r"(hi) : "l"(v));
    return __uint_as_float(lo) + __uint_as_float(hi);
}
__device__ __forceinline__ float tanh_fast(float x) {
    float y;
    asm("tanh.approx.f32 %0, %1;" : "=f"(y) : "f"(x));
    return y;
}
__device__ __forceinline__ float sigmoid_fast(float x) {
    return fmaf(0.5f, tanh_fast(0.5f * x), 0.5f);
}

#define QPAD 36   // padded quarter stride (floats): conflict-free, 16B aligned

__global__ __launch_bounds__(512, 1) void gru_kernel(
    const float* __restrict__ Whh_f, const float* __restrict__ bhh_f,
    const float* __restrict__ Whh_b, const float* __restrict__ bhh_b)
{
    const int b   = blockIdx.x & 31;
    const int dir = blockIdx.x >> 5;
    const float* Whh = dir ? Whh_b : Whh_f;
    const float* bhh = dir ? bhh_b : bhh_f;
    const int tid  = threadIdx.x;
    const int c    = tid >> 2;    // column 0..127
    const int q    = tid & 3;     // K-quarter
    const int lane = tid & 31;
    const int gb   = lane & ~3;   // group base lane

    // weights: gate g row = g*H + c, K slice [32q, 32q+32) -> 16 u64 per gate
    uint64_t wr[16], wz[16], wn_[16];
    {
        const ulonglong2* s0 = (const ulonglong2*)(Whh + (size_t)(0 * H + c) * H + q * 32);
        const ulonglong2* s1 = (const ulonglong2*)(Whh + (size_t)(1 * H + c) * H + q * 32);
        const ulonglong2* s2 = (const ulonglong2*)(Whh + (size_t)(2 * H + c) * H + q * 32);
#pragma unroll
        for (int j = 0; j < 8; j++) {
            ulonglong2 p0 = s0[j]; wr[2 * j] = p0.x; wr[2 * j + 1] = p0.y;
            ulonglong2 p1 = s1[j]; wz[2 * j] = p1.x; wz[2 * j + 1] = p1.y;
            ulonglong2 p2 = s2[j]; wn_[2 * j] = p2.x; wn_[2 * j + 1] = p2.y;
        }
    }
    const float biasN = bhh[2 * H + c];

    __shared__ __align__(16) float hs[2][4 * QPAD];
    for (int i = tid; i < 2 * 4 * QPAD; i += 512) ((float*)hs)[i] = 0.f;
    float hprev = 0.f;

    const float* xp = g_xp + ((size_t)dir * TLEN * BATCH + b) * G3;
    float xcur = (q < 3) ? xp[q * H + c] : 0.f;

    // hcat pointer with signed per-step stride
    float* hc = g_hcat + ((size_t)b * TLEN + (dir ? TLEN - 1 : 0)) * (2 * H) + dir * H + c;
    const int hcstep = dir ? -(2 * H) : (2 * H);

    __syncthreads();

    int par = 0;
    for (int t = 0; t < TLEN; t++) {
        float xnext = (q < 3 && t < TLEN - 1) ? xp[(size_t)(t + 1) * BATCH * G3 + q * H + c] : 0.f;

        const ulonglong2* h4 = (const ulonglong2*)(hs[par] + q * QPAD);
        uint64_t ar = 0, az = 0, an = 0;   // packed (0.f,0.f)
#pragma unroll
        for (int j = 0; j < 8; j++) {
            ulonglong2 p = h4[j];
            fma2(ar, wr[2 * j], p.x);  fma2(ar, wr[2 * j + 1], p.y);
            fma2(az, wz[2 * j], p.x);  fma2(az, wz[2 * j + 1], p.y);
            fma2(an, wn_[2 * j], p.x); fma2(an, wn_[2 * j + 1], p.y);
        }
        float dr = lohi_sum(ar), dz = lohi_sum(az), dn = lohi_sum(an);
        // butterfly over the 4-lane group
        dr += __shfl_xor_sync(0xffffffffu, dr, 1);
        dz += __shfl_xor_sync(0xffffffffu, dz, 1);
        dn += __shfl_xor_sync(0xffffffffu, dn, 1);
        dr += __shfl_xor_sync(0xffffffffu, dr, 2);
        dz += __shfl_xor_sync(0xffffffffu, dz, 2);
        dn += __shfl_xor_sync(0xffffffffu, dn, 2);
        // gather x values (xr/xz already include bih+bhh; xn includes bih only)
        float xr = __shfl_sync(0xffffffffu, xcur, gb + 0);
        float xz = __shfl_sync(0xffffffffu, xcur, gb + 1);
        float xn = __shfl_sync(0xffffffffu, xcur, gb + 2);

        float r = sigmoid_fast(xr + dr);
        float z = sigmoid_fast(xz + dz);
        float n = tanh_fast(xn + r * (dn + biasN));
        float hnew = (1.f - z) * n + z * hprev;
        hprev = hnew;

        int nb = par ^ 1;
        if (q == 0) {
            hs[nb][(c >> 5) * QPAD + (c & 31)] = hnew;
            hc[0] = hnew;
        }
        __syncthreads();
        par = nb;
        hc += hcstep;
        xcur = xnext;
    }
}

// ---------------------------------------------------------------------------
// K3: emissions = hcat @ Wlin^T + blin  (M=8192, N=9, K=256). Warp per row.
// ---------------------------------------------------------------------------
__global__ __launch_bounds__(256) void emis_kernel(
    const float* __restrict__ Wlin, const float* __restrict__ blin)
{
    __shared__ float wl[NL][2 * H];
    __shared__ float bl[NL];
    const int tid = threadIdx.x;
    for (int i = tid; i < NL * 2 * H; i += 256) wl[i / (2 * H)][i % (2 * H)] = Wlin[i];
    if (tid < NL) bl[tid] = blin[tid];
    __syncthreads();

    const int warp = tid >> 5, lane = tid & 31;
    const int row = blockIdx.x * 8 + warp;   // b*256 + t
    const float* h = g_hcat + (size_t)row * (2 * H);
    float hv[8];
#pragma unroll
    for (int i = 0; i < 8; i++) hv[i] = h[i * 32 + lane];
#pragma unroll
    for (int l = 0; l < NL; l++) {
        float s = 0.f;
#pragma unroll
        for (int i = 0; i < 8; i++) s += hv[i] * wl[l][i * 32 + lane];
#pragma unroll
        for (int off = 16; off; off >>= 1) s += __shfl_xor_sync(0xffffffffu, s, off);
        if (lane == 0) g_em[(size_t)row * NL + l] = s + bl[l];
    }
}

// ---------------------------------------------------------------------------
// K4: Viterbi + CRF log-likelihood, 8 warps per block (4 Viterbi + 4 CRF).
// ---------------------------------------------------------------------------
__global__ __launch_bounds__(256) void vitcrf_kernel(
    const float* __restrict__ trans, const float* __restrict__ startv,
    const float* __restrict__ endv, const int* __restrict__ labels,
    float* __restrict__ dout)
{
    const int w    = threadIdx.x >> 5;
    const int lane = threadIdx.x & 31;
    const int b    = blockIdx.x * 4 + (w >> 1);   // batch index
    const bool isV = (w & 1) == 0;

    float tr[NL];
#pragma unroll
    for (int i = 0; i < NL; i++) tr[i] = (lane < NL) ? trans[i * NL + lane] : 0.f;

    const float* em = g_em + (size_t)b * TLEN * NL;

    if (isV) {
        __shared__ unsigned char bp[4][TLEN - 1][NL];
        const int vw = w >> 1;
        float alpha = (lane < NL) ? startv[lane] + em[lane] : NEG_INF;
        float ecur = (lane < NL) ? em[NL + lane] : 0.f;
        for (int t = 1; t < TLEN; t++) {
            float enext = (t < TLEN - 1 && lane < NL) ? em[(t + 1) * NL + lane] : 0.f;
            float best = NEG_INF; int bi = 0;
#pragma unroll
            for (int i = 0; i < NL; i++) {
                float ai = __shfl_sync(0xffffffffu, alpha, i);
                float sc = ai + tr[i];
                if (sc > best) { best = sc; bi = i; }
            }
            if (lane < NL) {
                bp[vw][t - 1][lane] = (unsigned char)bi;
                alpha = best + ecur;
            }
            ecur = enext;
        }
        float v = (lane < NL) ? alpha + endv[lane] : NEG_INF;
        int idx = lane;
#pragma unroll
        for (int off = 16; off; off >>= 1) {
            float ov = __shfl_xor_sync(0xffffffffu, v, off);
            int   oi = __shfl_xor_sync(0xffffffffu, idx, off);
            if (ov > v || (ov == v && oi < idx)) { v = ov; idx = oi; }
        }
        __syncwarp();
        if (lane == 0) {
            int y = idx;
            float* outp = dout + b * TLEN;
            outp[TLEN - 1] = (float)y;
            for (int t = TLEN - 2; t >= 0; t--) {
                y = bp[vw][t][y];
                outp[t] = (float)y;
            }
        }
    } else {
        const int* lab = labels + b * TLEN;
        float s = 0.f;
        for (int t = lane; t < TLEN; t += 32) s += em[t * NL + lab[t]];
        for (int t = lane; t < TLEN - 1; t += 32) s += trans[lab[t] * NL + lab[t + 1]];
#pragma unroll
        for (int off = 16; off; off >>= 1) s += __shfl_xor_sync(0xffffffffu, s, off);
        float num = s + startv[lab[0]] + endv[lab[TLEN - 1]];

        float ca = (lane < NL) ? startv[lane] + em[lane] : NEG_INF;
        float ecur = (lane < NL) ? em[NL + lane] : 0.f;
        for (int t = 1; t < TLEN; t++) {
            float enext = (t < TLEN - 1 && lane < NL) ? em[(t + 1) * NL + lane] : 0.f;
            float vals[NL];
#pragma unroll
            for (int i = 0; i < NL; i++) {
                float ai = __shfl_sync(0xffffffffu, ca, i);
                vals[i] = ai + tr[i];
            }
            float m01 = fmaxf(vals[0], vals[1]), m23 = fmaxf(vals[2], vals[3]);
            float m45 = fmaxf(vals[4], vals[5]), m67 = fmaxf(vals[6], vals[7]);
            float m0123 = fmaxf(m01, m23), m4567 = fmaxf(m45, m67);
            float best = fmaxf(fmaxf(m0123, m4567), vals[8]);
            float ssum = 0.f;
#pragma unroll
            for (int i = 0; i < NL; i++) ssum += __expf(vals[i] - best);
            ca = (lane < NL) ? (best + __logf(ssum) + ecur) : NEG_INF;
            ecur = enext;
        }
        float v = (lane < NL) ? ca + endv[lane] : NEG_INF;
        float m = v;
#pragma unroll
        for (int off = 16; off; off >>= 1) m = fmaxf(m, __shfl_xor_sync(0xffffffffu, m, off));
        float ex = (lane < NL) ? __expf(v - m) : 0.f;
#pragma unroll
        for (int off = 16; off; off >>= 1) ex += __shfl_xor_sync(0xffffffffu, ex, off);
        if (lane == 0) g_llh[b] = num - (m + __logf(ex));
    }
}

// ---------------------------------------------------------------------------
// K5: loss = -mean(llh)
// ---------------------------------------------------------------------------
__global__ void loss_kernel(float* __restrict__ dout, int out_size)
{
    float v = g_llh[threadIdx.x];
#pragma unroll
    for (int off = 16; off; off >>= 1) v += __shfl_xor_sync(0xffffffffu, v, off);
    if (threadIdx.x == 0) dout[out_size - 1] = -(v / (float)BATCH);
}

// ---------------------------------------------------------------------------
extern "C" void kernel_launch(void* const* d_in, const int* in_sizes, int n_in,
                              void* d_out, int out_size)
{
    const int*   input_ids = (const int*)d_in[0];
    const int*   labels    = (const int*)d_in[2];
    const float* emb       = (const float*)d_in[3];
    const float* Wih_f     = (const float*)d_in[4];
    const float* Whh_f     = (const float*)d_in[5];
    const float* bih_f     = (const float*)d_in[6];
    const float* bhh_f     = (const float*)d_in[7];
    const float* Wih_b     = (const float*)d_in[8];
    const float* Whh_b     = (const float*)d_in[9];
    const float* bih_b     = (const float*)d_in[10];
    const float* bhh_b     = (const float*)d_in[11];
    const float* Wlin      = (const float*)d_in[12];
    const float* blin      = (const float*)d_in[13];
    const float* trans     = (const float*)d_in[14];
    const float* startv    = (const float*)d_in[15];
    const float* endv      = (const float*)d_in[16];
    float* out = (float*)d_out;

    conv_w_kernel<<<2 * G3, HID>>>(Wih_f, Wih_b);
    conv_a_kernel<<<BATCH * TLEN, 192>>>(input_ids, emb);
    dim3 ggrid((BATCH * TLEN) / BM, (2 * G3) / BN);
    gemm_xp_tc<<<ggrid, 256>>>(bih_f, bih_b, bhh_f, bhh_b);
    gru_kernel<<<64, 512>>>(Whh_f, bhh_f, Whh_b, bhh_b);
    emis_kernel<<<BATCH * TLEN / 8, 256>>>(Wlin, blin);
    vitcrf_kernel<<<8, 256>>>(trans, startv, endv, labels, out);
    loss_kernel<<<1, 32>>>(out, out_size);
}

// round 17
// speedup vs baseline: 1.9617x; 1.0903x over previous
#include <cuda_runtime.h>
#include <cuda_bf16.h>
#include <math.h>
#include <stdint.h>

// Problem constants
#define BATCH 32
#define TLEN  256
#define HID   768
#define H     128
#define G3    384   // 3*H
#define NL    9

#define NEG_INF (-1e30f)

// ---------------- scratch (device globals; no allocations allowed) ----------
// g_xp padded by one extra step so the GRU can prefetch x[t+1] unconditionally.
__device__ float g_xp[2 * TLEN * BATCH * G3 + BATCH * G3];
__device__ float g_hcat[BATCH * TLEN * 2 * H];    // [b][t][256]        8.4MB
__device__ float g_em[BATCH * TLEN * NL];         // emissions
__device__ float g_llh[BATCH];
__device__ __nv_bfloat16 g_wbf[2 * G3 * HID];     // [n][k] bf16 weights (f then b)
__device__ __nv_bfloat16 g_abf[BATCH * TLEN * HID]; // gathered A in bf16 (12.6MB)

// ---------------------------------------------------------------------------
// K0a: convert Wih_f / Wih_b -> bf16 panel  [768][768]
// ---------------------------------------------------------------------------
__global__ void conv_w_kernel(const float* __restrict__ Wf, const float* __restrict__ Wb)
{
    int n = blockIdx.x;           // 0..767
    int k = threadIdx.x;          // 0..767
    float v = (n < G3) ? Wf[n * HID + k] : Wb[(n - G3) * HID + k];
    g_wbf[(size_t)n * HID + k] = __float2bfloat16(v);
}

// ---------------------------------------------------------------------------
// K0b: gather emb rows by input_ids and convert to bf16 -> g_abf [8192][768]
// ---------------------------------------------------------------------------
__global__ __launch_bounds__(192) void conv_a_kernel(
    const int* __restrict__ ids, const float* __restrict__ emb)
{
    int m = blockIdx.x;                  // 0..8191
    int row = __ldg(&ids[m]);
    const float4* src = (const float4*)(emb + (size_t)row * HID);
    float4 v = src[threadIdx.x];
    __nv_bfloat162 lo = __float22bfloat162_rn(make_float2(v.x, v.y));
    __nv_bfloat162 hi = __float22bfloat162_rn(make_float2(v.z, v.w));
    uint2 u;
    u.x = *(uint32_t*)&lo; u.y = *(uint32_t*)&hi;
    *(uint2*)(g_abf + (size_t)m * HID + threadIdx.x * 4) = u;
}

// ---------------------------------------------------------------------------
// K1: input projection GEMM on tensor cores (bf16 HMMA), all-cp.async 3-stage.
//     Epilogue folds bih (always) and bhh (for r,z gate rows g<256) into g_xp.
// ---------------------------------------------------------------------------
#define BM 128
#define BN 128
#define BKC 32
#define ASZ (BM * BKC)   // bf16 elements per stage buffer
#define NK (HID / BKC)   // 24

__device__ __forceinline__ void ldsm4(uint32_t* r, uint32_t addr) {
    asm volatile("ldmatrix.sync.aligned.m8n8.x4.shared.b16 {%0,%1,%2,%3}, [%4];\n"
                 : "=r"(r[0]), "=r"(r[1]), "=r"(r[2]), "=r"(r[3]) : "r"(addr));
}
__device__ __forceinline__ void mma16816(float* c, const uint32_t* a, const uint32_t* b) {
    asm volatile(
        "mma.sync.aligned.m16n8k16.row.col.f32.bf16.bf16.f32 "
        "{%0,%1,%2,%3}, {%4,%5,%6,%7}, {%8,%9}, {%0,%1,%2,%3};\n"
        : "+f"(c[0]), "+f"(c[1]), "+f"(c[2]), "+f"(c[3])
        : "r"(a[0]), "r"(a[1]), "r"(a[2]), "r"(a[3]), "r"(b[0]), "r"(b[1]));
}
__device__ __forceinline__ void cpasync16(uint32_t dst, const void* src) {
    asm volatile("cp.async.ca.shared.global [%0], [%1], 16;\n" :: "r"(dst), "l"(src));
}

__global__ __launch_bounds__(256) void gemm_xp_tc(
    const float* __restrict__ bih_f, const float* __restrict__ bih_b,
    const float* __restrict__ bhh_f, const float* __restrict__ bhh_b)
{
    __shared__ __align__(16) __nv_bfloat16 As[3 * ASZ];
    __shared__ __align__(16) __nv_bfloat16 Bs[3 * ASZ];

    const int tid = threadIdx.x;
    const int m0 = blockIdx.x * BM;
    const int n0 = blockIdx.y * BN;

    const int lrow = tid >> 1;          // 0..127
    const int cpa  = (tid & 1) * 2;     // chunk base: 0 or 2 (8 bf16 per chunk)

    const __nv_bfloat16* aptr = g_abf + (size_t)(m0 + lrow) * HID + cpa * 8;
    const __nv_bfloat16* bptr = g_wbf + (size_t)(n0 + lrow) * HID + cpa * 8;

    const uint32_t as_base = (uint32_t)__cvta_generic_to_shared(As);
    const uint32_t bs_base = (uint32_t)__cvta_generic_to_shared(Bs);

    const int swz = (lrow >> 1) & 3;
    const uint32_t off0 = (uint32_t)((lrow * BKC + ((cpa ^ swz) << 3)) * 2);
    const uint32_t off1 = (uint32_t)((lrow * BKC + (((cpa + 1) ^ swz) << 3)) * 2);

    const int warp = tid >> 5, lane = tid & 31;
    const int wm = warp >> 2, wn = warp & 3;   // 2 x 4
    const int lr = lane & 7, lmi = lane >> 3;

    float acc[4][4][4];
#pragma unroll
    for (int i = 0; i < 4; i++)
#pragma unroll
        for (int j = 0; j < 4; j++)
#pragma unroll
            for (int q = 0; q < 4; q++) acc[i][j][q] = 0.f;

#pragma unroll
    for (int s = 0; s < 2; s++) {
        uint32_t sb = s * (ASZ * 2);
        cpasync16(as_base + sb + off0, aptr + s * BKC);
        cpasync16(as_base + sb + off1, aptr + s * BKC + 8);
        cpasync16(bs_base + sb + off0, bptr + s * BKC);
        cpasync16(bs_base + sb + off1, bptr + s * BKC + 8);
        asm volatile("cp.async.commit_group;\n");
    }

    int sc = 0;
    int si = 2;
    for (int ch = 0; ch < NK; ch++) {
        __syncthreads();
        if (ch + 2 < NK) {
            const uint32_t sb = si * (ASZ * 2);
            const int kk = (ch + 2) * BKC;
            cpasync16(as_base + sb + off0, aptr + kk);
            cpasync16(as_base + sb + off1, aptr + kk + 8);
            cpasync16(bs_base + sb + off0, bptr + kk);
            cpasync16(bs_base + sb + off1, bptr + kk + 8);
            asm volatile("cp.async.commit_group;\n");
            asm volatile("cp.async.wait_group 2;\n");
            si = (si == 2) ? 0 : si + 1;
        } else {
            asm volatile("cp.async.wait_group 0;\n");
        }
        __syncthreads();

        const uint32_t ab = as_base + sc * (ASZ * 2);
        const uint32_t bb = bs_base + sc * (ASZ * 2);
#pragma unroll
        for (int k16 = 0; k16 < 2; k16++) {
            uint32_t afr[4][4];
#pragma unroll
            for (int am = 0; am < 4; am++) {
                int rowA = wm * 64 + am * 16 + lr + ((lmi & 1) << 3);
                int cA = k16 * 2 + (lmi >> 1);
                uint32_t addr = ab + (uint32_t)((rowA * BKC + ((cA ^ ((rowA >> 1) & 3)) << 3)) * 2);
                ldsm4(afr[am], addr);
            }
            uint32_t bfr[4][2];
#pragma unroll
            for (int p = 0; p < 2; p++) {
                int rowB = wn * 32 + p * 16 + lr + ((lmi >> 1) << 3);
                int cB = k16 * 2 + (lmi & 1);
                uint32_t addr = bb + (uint32_t)((rowB * BKC + ((cB ^ ((rowB >> 1) & 3)) << 3)) * 2);
                uint32_t r[4];
                ldsm4(r, addr);
                bfr[2 * p][0] = r[0]; bfr[2 * p][1] = r[1];
                bfr[2 * p + 1][0] = r[2]; bfr[2 * p + 1][1] = r[3];
            }
#pragma unroll
            for (int am = 0; am < 4; am++)
#pragma unroll
                for (int an = 0; an < 4; an++)
                    mma16816(acc[am][an], afr[am], bfr[an]);
        }
        sc = (sc == 2) ? 0 : sc + 1;
    }

#pragma unroll
    for (int am = 0; am < 4; am++) {
#pragma unroll
        for (int an = 0; an < 4; an++) {
            int n = n0 + wn * 32 + an * 8 + (lane & 3) * 2;
            int dir = (n >= G3) ? 1 : 0;
            int g = n - dir * G3;
            float b0 = dir ? bih_b[g] : bih_f[g];
            float b1 = dir ? bih_b[g + 1] : bih_f[g + 1];
            // fold bhh for r,z gate rows (g < 2H); n-gate bias stays in gru.
            if (g < 2 * H) {
                b0 += dir ? bhh_b[g] : bhh_f[g];
                b1 += dir ? bhh_b[g + 1] : bhh_f[g + 1];
            }
#pragma unroll
            for (int half = 0; half < 2; half++) {
                int m = m0 + wm * 64 + am * 16 + (lane >> 2) + half * 8;
                int b = m >> 8, t = m & 255;
                int step = dir ? (TLEN - 1 - t) : t;
                float2 v;
                v.x = acc[am][an][2 * half + 0] + b0;
                v.y = acc[am][an][2 * half + 1] + b1;
                *(float2*)&g_xp[(((size_t)dir * TLEN + step) * BATCH + b) * G3 + g] = v;
            }
        }
    }
}

// ---------------------------------------------------------------------------
// K2: GRU recurrence — 512 threads, 4-thread groups per column (c, K-quarter q).
//     REGISTER DIET vs R12: unconditional x prefetch (padded g_xp, no
//     predicates), hcat base pointer + branch-local tt, inlined shfl lanes.
//     Target: <=126 regs so ptxas does not spill the 96 weight registers.
// ---------------------------------------------------------------------------
__device__ __forceinline__ void fma2(uint64_t& d, uint64_t a, uint64_t b) {
    asm("fma.rn.f32x2 %0, %1, %2, %0;" : "+l"(d) : "l"(a), "l"(b));
}
__device__ __forceinline__ float lohi_sum(uint64_t v) {
    uint32_t lo, hi;
    asm("mov.b64 {%0,%1}, %2;" : "=r"(lo), "=r"(hi) : "l"(v));
    return __uint_as_float(lo) + __uint_as_float(hi);
}
__device__ __forceinline__ float tanh_fast(float x) {
    float y;
    asm("tanh.approx.f32 %0, %1;" : "=f"(y) : "f"(x));
    return y;
}
__device__ __forceinline__ float sigmoid_fast(float x) {
    return fmaf(0.5f, tanh_fast(0.5f * x), 0.5f);
}

#define QPAD 36   // padded quarter stride (floats): conflict-free, 16B aligned

__global__ __launch_bounds__(512, 1) void gru_kernel(
    const float* __restrict__ Whh_f, const float* __restrict__ bhh_f,
    const float* __restrict__ Whh_b, const float* __restrict__ bhh_b)
{
    const int b   = blockIdx.x & 31;
    const int dir = blockIdx.x >> 5;
    const float* Whh = dir ? Whh_b : Whh_f;
    const float* bhh = dir ? bhh_b : bhh_f;
    const int tid  = threadIdx.x;
    const int c    = tid >> 2;    // column 0..127
    const int q    = tid & 3;     // K-quarter

    // weights: gate g row = g*H + c, K slice [32q, 32q+32) -> 16 u64 per gate
    uint64_t wr[16], wz[16], wn_[16];
    {
        const ulonglong2* s0 = (const ulonglong2*)(Whh + (size_t)(0 * H + c) * H + q * 32);
        const ulonglong2* s1 = (const ulonglong2*)(Whh + (size_t)(1 * H + c) * H + q * 32);
        const ulonglong2* s2 = (const ulonglong2*)(Whh + (size_t)(2 * H + c) * H + q * 32);
#pragma unroll
        for (int j = 0; j < 8; j++) {
            ulonglong2 p0 = s0[j]; wr[2 * j] = p0.x; wr[2 * j + 1] = p0.y;
            ulonglong2 p1 = s1[j]; wz[2 * j] = p1.x; wz[2 * j + 1] = p1.y;
            ulonglong2 p2 = s2[j]; wn_[2 * j] = p2.x; wn_[2 * j + 1] = p2.y;
        }
    }
    const float biasN = bhh[2 * H + c];

    __shared__ __align__(16) float hs[2][4 * QPAD];
    for (int i = tid; i < 2 * 4 * QPAD; i += 512) ((float*)hs)[i] = 0.f;
    float hprev = 0.f;

    // x pointer for this thread's quarter slot (q==3 reads in-bounds garbage,
    // never consumed — padding on g_xp makes every access safe).
    const float* xq = g_xp + ((size_t)dir * TLEN * BATCH + b) * G3 + q * H + c;
    float xnext = xq[0];

    // uniform hcat base for this (dir,b); per-step index computed in-branch
    float* hcb = g_hcat + (size_t)b * TLEN * (2 * H) + dir * H + c;

    __syncthreads();

    int par = 0;
    for (int t = 0; t < TLEN; t++) {
        float xcur = xnext;
        xnext = xq[(size_t)(t + 1) * BATCH * G3];   // always in-bounds (padded)

        const ulonglong2* h4 = (const ulonglong2*)(hs[par] + q * QPAD);
        uint64_t ar = 0, az = 0, an = 0;   // packed (0.f,0.f)
#pragma unroll
        for (int j = 0; j < 8; j++) {
            ulonglong2 p = h4[j];
            fma2(ar, wr[2 * j], p.x);  fma2(ar, wr[2 * j + 1], p.y);
            fma2(az, wz[2 * j], p.x);  fma2(az, wz[2 * j + 1], p.y);
            fma2(an, wn_[2 * j], p.x); fma2(an, wn_[2 * j + 1], p.y);
        }
        float dr = lohi_sum(ar), dz = lohi_sum(az), dn = lohi_sum(an);
        // butterfly over the 4-lane group
        dr += __shfl_xor_sync(0xffffffffu, dr, 1);
        dz += __shfl_xor_sync(0xffffffffu, dz, 1);
        dn += __shfl_xor_sync(0xffffffffu, dn, 1);
        dr += __shfl_xor_sync(0xffffffffu, dr, 2);
        dz += __shfl_xor_sync(0xffffffffu, dz, 2);
        dn += __shfl_xor_sync(0xffffffffu, dn, 2);
        // gather x values (xr/xz already include bih+bhh; xn includes bih only)
        float xr = __shfl_sync(0xffffffffu, xcur, (tid & 28));
        float xz = __shfl_sync(0xffffffffu, xcur, (tid & 28) + 1);
        float xn = __shfl_sync(0xffffffffu, xcur, (tid & 28) + 2);

        float r = sigmoid_fast(xr + dr);
        float z = sigmoid_fast(xz + dz);
        float n = tanh_fast(xn + r * (dn + biasN));
        float hnew = (1.f - z) * n + z * hprev;
        hprev = hnew;

        int nb = par ^ 1;
        if (q == 0) {
            hs[nb][(c >> 5) * QPAD + (c & 31)] = hnew;
            int tt = dir ? (TLEN - 1 - t) : t;
            hcb[(size_t)tt * (2 * H)] = hnew;
        }
        __syncthreads();
        par = nb;
    }
}

// ---------------------------------------------------------------------------
// K3: emissions = hcat @ Wlin^T + blin  (M=8192, N=9, K=256). Warp per row.
// ---------------------------------------------------------------------------
__global__ __launch_bounds__(256) void emis_kernel(
    const float* __restrict__ Wlin, const float* __restrict__ blin)
{
    __shared__ float wl[NL][2 * H];
    __shared__ float bl[NL];
    const int tid = threadIdx.x;
    for (int i = tid; i < NL * 2 * H; i += 256) wl[i / (2 * H)][i % (2 * H)] = Wlin[i];
    if (tid < NL) bl[tid] = blin[tid];
    __syncthreads();

    const int warp = tid >> 5, lane = tid & 31;
    const int row = blockIdx.x * 8 + warp;   // b*256 + t
    const float* h = g_hcat + (size_t)row * (2 * H);
    float hv[8];
#pragma unroll
    for (int i = 0; i < 8; i++) hv[i] = h[i * 32 + lane];
#pragma unroll
    for (int l = 0; l < NL; l++) {
        float s = 0.f;
#pragma unroll
        for (int i = 0; i < 8; i++) s += hv[i] * wl[l][i * 32 + lane];
#pragma unroll
        for (int off = 16; off; off >>= 1) s += __shfl_xor_sync(0xffffffffu, s, off);
        if (lane == 0) g_em[(size_t)row * NL + l] = s + bl[l];
    }
}

// ---------------------------------------------------------------------------
// K4: Viterbi + CRF log-likelihood, 8 warps per block (4 Viterbi + 4 CRF).
// ---------------------------------------------------------------------------
__global__ __launch_bounds__(256) void vitcrf_kernel(
    const float* __restrict__ trans, const float* __restrict__ startv,
    const float* __restrict__ endv, const int* __restrict__ labels,
    float* __restrict__ dout)
{
    const int w    = threadIdx.x >> 5;
    const int lane = threadIdx.x & 31;
    const int b    = blockIdx.x * 4 + (w >> 1);   // batch index
    const bool isV = (w & 1) == 0;

    float tr[NL];
#pragma unroll
    for (int i = 0; i < NL; i++) tr[i] = (lane < NL) ? trans[i * NL + lane] : 0.f;

    const float* em = g_em + (size_t)b * TLEN * NL;

    if (isV) {
        __shared__ unsigned char bp[4][TLEN - 1][NL];
        const int vw = w >> 1;
        float alpha = (lane < NL) ? startv[lane] + em[lane] : NEG_INF;
        float ecur = (lane < NL) ? em[NL + lane] : 0.f;
        for (int t = 1; t < TLEN; t++) {
            float enext = (t < TLEN - 1 && lane < NL) ? em[(t + 1) * NL + lane] : 0.f;
            float best = NEG_INF; int bi = 0;
#pragma unroll
            for (int i = 0; i < NL; i++) {
                float ai = __shfl_sync(0xffffffffu, alpha, i);
                float sc = ai + tr[i];
                if (sc > best) { best = sc; bi = i; }
            }
            if (lane < NL) {
                bp[vw][t - 1][lane] = (unsigned char)bi;
                alpha = best + ecur;
            }
            ecur = enext;
        }
        float v = (lane < NL) ? alpha + endv[lane] : NEG_INF;
        int idx = lane;
#pragma unroll
        for (int off = 16; off; off >>= 1) {
            float ov = __shfl_xor_sync(0xffffffffu, v, off);
            int   oi = __shfl_xor_sync(0xffffffffu, idx, off);
            if (ov > v || (ov == v && oi < idx)) { v = ov; idx = oi; }
        }
        __syncwarp();
        if (lane == 0) {
            int y = idx;
            float* outp = dout + b * TLEN;
            outp[TLEN - 1] = (float)y;
            for (int t = TLEN - 2; t >= 0; t--) {
                y = bp[vw][t][y];
                outp[t] = (float)y;
            }
        }
    } else {
        const int* lab = labels + b * TLEN;
        float s = 0.f;
        for (int t = lane; t < TLEN; t += 32) s += em[t * NL + lab[t]];
        for (int t = lane; t < TLEN - 1; t += 32) s += trans[lab[t] * NL + lab[t + 1]];
#pragma unroll
        for (int off = 16; off; off >>= 1) s += __shfl_xor_sync(0xffffffffu, s, off);
        float num = s + startv[lab[0]] + endv[lab[TLEN - 1]];

        float ca = (lane < NL) ? startv[lane] + em[lane] : NEG_INF;
        float ecur = (lane < NL) ? em[NL + lane] : 0.f;
        for (int t = 1; t < TLEN; t++) {
            float enext = (t < TLEN - 1 && lane < NL) ? em[(t + 1) * NL + lane] : 0.f;
            float vals[NL];
#pragma unroll
            for (int i = 0; i < NL; i++) {
                float ai = __shfl_sync(0xffffffffu, ca, i);
                vals[i] = ai + tr[i];
            }
            float m01 = fmaxf(vals[0], vals[1]), m23 = fmaxf(vals[2], vals[3]);
            float m45 = fmaxf(vals[4], vals[5]), m67 = fmaxf(vals[6], vals[7]);
            float m0123 = fmaxf(m01, m23), m4567 = fmaxf(m45, m67);
            float best = fmaxf(fmaxf(m0123, m4567), vals[8]);
            float ssum = 0.f;
#pragma unroll
            for (int i = 0; i < NL; i++) ssum += __expf(vals[i] - best);
            ca = (lane < NL) ? (best + __logf(ssum) + ecur) : NEG_INF;
            ecur = enext;
        }
        float v = (lane < NL) ? ca + endv[lane] : NEG_INF;
        float m = v;
#pragma unroll
        for (int off = 16; off; off >>= 1) m = fmaxf(m, __shfl_xor_sync(0xffffffffu, m, off));
        float ex = (lane < NL) ? __expf(v - m) : 0.f;
#pragma unroll
        for (int off = 16; off; off >>= 1) ex += __shfl_xor_sync(0xffffffffu, ex, off);
        if (lane == 0) g_llh[b] = num - (m + __logf(ex));
    }
}

// ---------------------------------------------------------------------------
// K5: loss = -mean(llh)
// ---------------------------------------------------------------------------
__global__ void loss_kernel(float* __restrict__ dout, int out_size)
{
    float v = g_llh[threadIdx.x];
#pragma unroll
    for (int off = 16; off; off >>= 1) v += __shfl_xor_sync(0xffffffffu, v, off);
    if (threadIdx.x == 0) dout[out_size - 1] = -(v / (float)BATCH);
}

// ---------------------------------------------------------------------------
extern "C" void kernel_launch(void* const* d_in, const int* in_sizes, int n_in,
                              void* d_out, int out_size)
{
    const int*   input_ids = (const int*)d_in[0];
    const int*   labels    = (const int*)d_in[2];
    const float* emb       = (const float*)d_in[3];
    const float* Wih_f     = (const float*)d_in[4];
    const float* Whh_f     = (const float*)d_in[5];
    const float* bih_f     = (const float*)d_in[6];
    const float* bhh_f     = (const float*)d_in[7];
    const float* Wih_b     = (const float*)d_in[8];
    const float* Whh_b     = (const float*)d_in[9];
    const float* bih_b     = (const float*)d_in[10];
    const float* bhh_b     = (const float*)d_in[11];
    const float* Wlin      = (const float*)d_in[12];
    const float* blin      = (const float*)d_in[13];
    const float* trans     = (const float*)d_in[14];
    const float* startv    = (const float*)d_in[15];
    const float* endv      = (const float*)d_in[16];
    float* out = (float*)d_out;

    conv_w_kernel<<<2 * G3, HID>>>(Wih_f, Wih_b);
    conv_a_kernel<<<BATCH * TLEN, 192>>>(input_ids, emb);
    dim3 ggrid((BATCH * TLEN) / BM, (2 * G3) / BN);
    gemm_xp_tc<<<ggrid, 256>>>(bih_f, bih_b, bhh_f, bhh_b);
    gru_kernel<<<64, 512>>>(Whh_f, bhh_f, Whh_b, bhh_b);
    emis_kernel<<<BATCH * TLEN / 8, 256>>>(Wlin, blin);
    vitcrf_kernel<<<8, 256>>>(trans, startv, endv, labels, out);
    loss_kernel<<<1, 32>>>(out, out_size);
}